// round 1
// baseline (speedup 1.0000x reference)
#include <cuda_runtime.h>
#include <cuda_bf16.h>
#include <math.h>

namespace {

constexpr int L   = 10;
constexpr int NH  = L * L;     // 100 harmonics
constexpr int NPB = 96;        // points per block (= blockDim.x)
constexpr int PAD = 101;       // smem row stride in floats; 101 mod 32 = 5 (odd) -> conflict-free STS
constexpr double PI_D = 3.141592653589793238462643383279502884;

// ---- compile-time math (all constants folded to immediates) ----
constexpr double csqrt(double x) {
    double r = x > 1.0 ? x : 1.0;
    for (int i = 0; i < 100; ++i) r = 0.5 * (r + x / r);
    return r;
}
constexpr double factd(int n) {
    double r = 1.0;
    for (int i = 2; i <= n; ++i) r *= (double)i;
    return r;
}
constexpr double SQRT2_D = csqrt(2.0);
// Standard real-SH normalization
constexpr double Kd(int l, int m) {
    return csqrt((2.0 * l + 1.0) / (4.0 * PI_D) * factd(l - m) / factd(l + m));
}
// K-hat: fold the sqrt(2) for m>0 directly into the scaled Legendre chain
constexpr double Kh(int l, int m) {
    return (m > 0 ? SQRT2_D : 1.0) * Kd(l, m);
}

struct Tabs {
    float k00;        // Qhat[0][0]
    float dm[L];      // m>=1 : Qhat[m][m]   = dm[m] * s * Qhat[m-1][m-1]
    float em[L];      // m<L-1: Qhat[m+1][m] = em[m] * x * Qhat[m][m]
    float A[L][L];    // l>=m+2: Qhat[l][m] = A*x*Qhat[l-1][m] + B*Qhat[l-2][m]
    float B[L][L];
};

constexpr Tabs make_tabs() {
    Tabs t{};
    t.k00 = (float)Kh(0, 0);
    for (int m = 1; m < L; ++m)
        t.dm[m] = (float)(-(2.0 * m - 1.0) * Kh(m, m) / Kh(m - 1, m - 1));
    for (int m = 0; m + 1 < L; ++m)
        t.em[m] = (float)((2.0 * m + 1.0) * Kh(m + 1, m) / Kh(m, m));
    for (int m = 0; m < L; ++m)
        for (int l = m + 2; l < L; ++l) {
            t.A[l][m] = (float)((2.0 * l - 1.0) / (double)(l - m) * Kh(l, m) / Kh(l - 1, m));
            t.B[l][m] = (float)(-(l + m - 1.0) / (double)(l - m) * Kh(l, m) / Kh(l - 2, m));
        }
    return t;
}
constexpr Tabs TB = make_tabs();

template <int I> struct IC { static constexpr int v = I; };
template <int S, int E, class F>
__device__ __forceinline__ void unrolled(F&& f) {
    if constexpr (S < E) {
        f(IC<S>{});
        unrolled<S + 1, E>(static_cast<F&&>(f));
    }
}

} // namespace

__global__ __launch_bounds__(NPB) void sh_kernel(const float2* __restrict__ ll,
                                                 float* __restrict__ out, int N) {
    __shared__ float sm[NPB * PAD];   // 96*101*4 = 38784 B

    const int t  = threadIdx.x;
    const int p0 = blockIdx.x * NPB;
    const int p  = p0 + t;

    if (p < N) {
        const float2 v  = ll[p];
        const float phi = (v.x + 180.0f) * 0.017453292519943295f;
        const float th  = (v.y + 90.0f)  * 0.017453292519943295f;
        float s, x, s1, c1;
        sincosf(th,  &s,  &x);    // s = sin(theta), x = cos(theta)
        sincosf(phi, &s1, &c1);   // base angle for cos(m*phi)/sin(m*phi) recurrence

        float* row = sm + t * PAD;

        float Qmm = 0.0f;         // Qhat[m][m] running value
        float cm = 1.0f, smv = 0.0f;  // cos(m*phi), sin(m*phi)

        unrolled<0, L>([&](auto mI) {
            constexpr int m = decltype(mI)::v;

            // update diagonal Qhat and trig recurrences
            if constexpr (m == 0) {
                Qmm = TB.k00;
            } else if constexpr (m == 1) {
                constexpr float d = TB.dm[1];
                Qmm = d * (s * Qmm);
                cm = c1; smv = s1;
            } else {
                constexpr float d = TB.dm[m];
                Qmm = d * (s * Qmm);
                const float cn = fmaf(cm, c1, -(smv * s1));
                const float sn = fmaf(smv, c1,  (cm * s1));
                cm = cn; smv = sn;
            }

            // emit (l = m)
            if constexpr (m == 0) {
                row[0] = Qmm;                       // idx = l*l + l = 0
            } else {
                row[m * m + 2 * m] = Qmm * cm;      // +m
                row[m * m]         = Qmm * smv;     // -m
            }

            if constexpr (m + 1 < L) {
                constexpr float e = TB.em[m];
                float Q1 = e * (x * Qmm);           // Qhat[m+1][m]
                constexpr int l1 = m + 1;
                if constexpr (m == 0) {
                    row[l1 * l1 + l1] = Q1;
                } else {
                    row[l1 * l1 + l1 + m] = Q1 * cm;
                    row[l1 * l1 + l1 - m] = Q1 * smv;
                }
                float Q2 = Qmm;
                unrolled<m + 2, L>([&](auto lI) {
                    constexpr int l = decltype(lI)::v;
                    constexpr float a = TB.A[l][m];
                    constexpr float b = TB.B[l][m];
                    const float Qn = fmaf(x * Q1, a, b * Q2);
                    if constexpr (m == 0) {
                        row[l * l + l] = Qn;
                    } else {
                        row[l * l + l + m] = Qn * cm;
                        row[l * l + l - m] = Qn * smv;
                    }
                    Q2 = Q1; Q1 = Qn;
                });
            }
        });
    }

    __syncthreads();

    // Coalesced copy: each warp streams whole point-rows, lanes contiguous.
    const int warp = t >> 5;
    const int lane = t & 31;
    for (int pp = warp; pp < NPB; pp += NPB / 32) {
        const int gp = p0 + pp;
        if (gp >= N) break;
        const float* r = sm + pp * PAD;
        float* o = out + (size_t)gp * NH;
        #pragma unroll
        for (int j = 0; j < 4; ++j) {
            const int jj = lane + 32 * j;
            if (jj < NH) o[jj] = r[jj];
        }
    }
}

extern "C" void kernel_launch(void* const* d_in, const int* in_sizes, int n_in,
                              void* d_out, int out_size) {
    const float2* ll = (const float2*)d_in[0];
    float* out = (float*)d_out;
    const int N = in_sizes[0] / 2;          // lonlat is [N,2] fp32
    const int grid = (N + NPB - 1) / NPB;
    sh_kernel<<<grid, NPB>>>(ll, out, N);
}

// round 2
// speedup vs baseline: 1.2868x; 1.2868x over previous
#include <cuda_runtime.h>
#include <cuda_bf16.h>
#include <math.h>

namespace {

constexpr int L   = 10;
constexpr int NH  = L * L;     // 100 harmonics
constexpr int NPB = 64;        // points per block = threads per block (2 warps)
constexpr int PAD = 101;       // odd stride -> conflict-free scalar STS/LDS
constexpr double PI_D = 3.141592653589793238462643383279502884;

// ---- compile-time math (all constants folded to FFMA immediates) ----
constexpr double csqrt(double x) {
    double r = x > 1.0 ? x : 1.0;
    for (int i = 0; i < 100; ++i) r = 0.5 * (r + x / r);
    return r;
}
constexpr double factd(int n) {
    double r = 1.0;
    for (int i = 2; i <= n; ++i) r *= (double)i;
    return r;
}
constexpr double SQRT2_D = csqrt(2.0);
constexpr double Kd(int l, int m) {
    return csqrt((2.0 * l + 1.0) / (4.0 * PI_D) * factd(l - m) / factd(l + m));
}
constexpr double Kh(int l, int m) {
    return (m > 0 ? SQRT2_D : 1.0) * Kd(l, m);
}

struct Tabs {
    float k00;
    float dm[L];
    float em[L];
    float A[L][L];
    float B[L][L];
};

constexpr Tabs make_tabs() {
    Tabs t{};
    t.k00 = (float)Kh(0, 0);
    for (int m = 1; m < L; ++m)
        t.dm[m] = (float)(-(2.0 * m - 1.0) * Kh(m, m) / Kh(m - 1, m - 1));
    for (int m = 0; m + 1 < L; ++m)
        t.em[m] = (float)((2.0 * m + 1.0) * Kh(m + 1, m) / Kh(m, m));
    for (int m = 0; m < L; ++m)
        for (int l = m + 2; l < L; ++l) {
            t.A[l][m] = (float)((2.0 * l - 1.0) / (double)(l - m) * Kh(l, m) / Kh(l - 1, m));
            t.B[l][m] = (float)(-(l + m - 1.0) / (double)(l - m) * Kh(l, m) / Kh(l - 2, m));
        }
    return t;
}
constexpr Tabs TB = make_tabs();

template <int I> struct IC { static constexpr int v = I; };
template <int S, int E, class F>
__device__ __forceinline__ void unrolled(F&& f) {
    if constexpr (S < E) {
        f(IC<S>{});
        unrolled<S + 1, E>(static_cast<F&&>(f));
    }
}

} // namespace

__global__ __launch_bounds__(NPB) void sh_kernel(const float2* __restrict__ ll,
                                                 float* __restrict__ out, int N) {
    __shared__ float sm[NPB * PAD];   // 64*101*4 = 25856 B -> 8 blocks/SM

    const int t    = threadIdx.x;
    const int lane = t & 31;
    const int wslc = (t >> 5) * (32 * PAD);   // this warp's smem slice
    const int p0   = blockIdx.x * NPB + (t & ~31);  // first point of this warp
    const int p    = p0 + lane;

    // ---------------- compute phase (warp-local) ----------------
    if (p < N) {
        const float2 v  = ll[p];
        const float phi = (v.x + 180.0f) * 0.017453292519943295f;
        const float th  = (v.y + 90.0f)  * 0.017453292519943295f;
        float s, x, s1, c1;
        __sincosf(th,  &s,  &x);    // s = sin(theta), x = cos(theta)
        __sincosf(phi, &s1, &c1);

        float* row = sm + wslc + lane * PAD;

        float Qmm = 0.0f;
        float cm = 1.0f, smv = 0.0f;

        unrolled<0, L>([&](auto mI) {
            constexpr int m = decltype(mI)::v;

            if constexpr (m == 0) {
                Qmm = TB.k00;
            } else if constexpr (m == 1) {
                constexpr float d = TB.dm[1];
                Qmm = d * (s * Qmm);
                cm = c1; smv = s1;
            } else {
                constexpr float d = TB.dm[m];
                Qmm = d * (s * Qmm);
                const float cn = fmaf(cm, c1, -(smv * s1));
                const float sn = fmaf(smv, c1,  (cm * s1));
                cm = cn; smv = sn;
            }

            if constexpr (m == 0) {
                row[0] = Qmm;
            } else {
                row[m * m + 2 * m] = Qmm * cm;
                row[m * m]         = Qmm * smv;
            }

            if constexpr (m + 1 < L) {
                constexpr float e = TB.em[m];
                float Q1 = e * (x * Qmm);
                constexpr int l1 = m + 1;
                if constexpr (m == 0) {
                    row[l1 * l1 + l1] = Q1;
                } else {
                    row[l1 * l1 + l1 + m] = Q1 * cm;
                    row[l1 * l1 + l1 - m] = Q1 * smv;
                }
                float Q2 = Qmm;
                unrolled<m + 2, L>([&](auto lI) {
                    constexpr int l = decltype(lI)::v;
                    constexpr float a = TB.A[l][m];
                    constexpr float b = TB.B[l][m];
                    const float Qn = fmaf(x * Q1, a, b * Q2);
                    if constexpr (m == 0) {
                        row[l * l + l] = Qn;
                    } else {
                        row[l * l + l + m] = Qn * cm;
                        row[l * l + l - m] = Qn * smv;
                    }
                    Q2 = Q1; Q1 = Qn;
                });
            }
        });
    }

    __syncwarp();

    // ---------------- copy phase (warp copies its own 32 rows) ----------------
    #pragma unroll 4
    for (int r = 0; r < 32; ++r) {
        const int gp = p0 + r;
        if (gp >= N) break;
        const float* rp = sm + wslc + r * PAD;
        float* o = out + (size_t)gp * NH;
        #pragma unroll
        for (int j = 0; j < 3; ++j)
            __stcs(o + lane + 32 * j, rp[lane + 32 * j]);
        if (lane < 4)
            __stcs(o + 96 + lane, rp[96 + lane]);
    }
}

extern "C" void kernel_launch(void* const* d_in, const int* in_sizes, int n_in,
                              void* d_out, int out_size) {
    const float2* ll = (const float2*)d_in[0];
    float* out = (float*)d_out;
    const int N = in_sizes[0] / 2;
    const int grid = (N + NPB - 1) / NPB;
    sh_kernel<<<grid, NPB>>>(ll, out, N);
}

// round 3
// speedup vs baseline: 1.3182x; 1.0244x over previous
#include <cuda_runtime.h>
#include <cuda_bf16.h>
#include <math.h>

namespace {

constexpr int L    = 10;
constexpr int NH   = L * L;      // 100 harmonics
constexpr int NPB  = 64;         // threads per block (2 warps), 1 point/thread
constexpr int CHK  = NH / 4;     // 25 float4 chunks per point
constexpr int QSTR = 132;        // words between chunk-rows (132 mod 32 = 4 -> conflict-free phases)
constexpr int WSLC = CHK * QSTR; // 3300 words per warp slice (13200 B)
constexpr double PI_D = 3.141592653589793238462643383279502884;

// ---- compile-time math (all constants folded to FFMA immediates) ----
constexpr double csqrt(double x) {
    double r = x > 1.0 ? x : 1.0;
    for (int i = 0; i < 100; ++i) r = 0.5 * (r + x / r);
    return r;
}
constexpr double factd(int n) {
    double r = 1.0;
    for (int i = 2; i <= n; ++i) r *= (double)i;
    return r;
}
constexpr double SQRT2_D = csqrt(2.0);
constexpr double Kd(int l, int m) {
    return csqrt((2.0 * l + 1.0) / (4.0 * PI_D) * factd(l - m) / factd(l + m));
}
constexpr double Kh(int l, int m) {
    return (m > 0 ? SQRT2_D : 1.0) * Kd(l, m);
}

struct Tabs {
    float k00;
    float dm[L];
    float em[L];
    float A[L][L];
    float B[L][L];
};

constexpr Tabs make_tabs() {
    Tabs t{};
    t.k00 = (float)Kh(0, 0);
    for (int m = 1; m < L; ++m)
        t.dm[m] = (float)(-(2.0 * m - 1.0) * Kh(m, m) / Kh(m - 1, m - 1));
    for (int m = 0; m + 1 < L; ++m)
        t.em[m] = (float)((2.0 * m + 1.0) * Kh(m + 1, m) / Kh(m, m));
    for (int m = 0; m < L; ++m)
        for (int l = m + 2; l < L; ++l) {
            t.A[l][m] = (float)((2.0 * l - 1.0) / (double)(l - m) * Kh(l, m) / Kh(l - 1, m));
            t.B[l][m] = (float)(-(l + m - 1.0) / (double)(l - m) * Kh(l, m) / Kh(l - 2, m));
        }
    return t;
}
constexpr Tabs TB = make_tabs();

template <int I> struct IC { static constexpr int v = I; };
template <int S, int E, class F>
__device__ __forceinline__ void unrolled(F&& f) {
    if constexpr (S < E) {
        f(IC<S>{});
        unrolled<S + 1, E>(static_cast<F&&>(f));
    }
}

} // namespace

__global__ __launch_bounds__(NPB) void sh_kernel(const float2* __restrict__ ll,
                                                 float* __restrict__ out, int N) {
    __shared__ float smbuf[(NPB / 32) * WSLC];   // 2 * 13200 B = 26400 B

    const int t    = threadIdx.x;
    const int lane = t & 31;
    float* sw      = smbuf + (t >> 5) * WSLC;          // this warp's slice
    const int p0   = blockIdx.x * NPB + (t & ~31);     // first point of this warp
    const int p    = p0 + lane;

    // ---------------- compute phase: all 100 values into registers ----------------
    float y[NH];

    {
        float2 v = (p < N) ? ll[p] : ll[0];
        const float phi = (v.x + 180.0f) * 0.017453292519943295f;
        const float th  = (v.y + 90.0f)  * 0.017453292519943295f;
        float s, x, s1, c1;
        __sincosf(th,  &s,  &x);     // s = sin(theta), x = cos(theta)
        __sincosf(phi, &s1, &c1);

        float Qmm = 0.0f;
        float cm = 1.0f, smv = 0.0f;

        unrolled<0, L>([&](auto mI) {
            constexpr int m = decltype(mI)::v;

            if constexpr (m == 0) {
                Qmm = TB.k00;
            } else if constexpr (m == 1) {
                constexpr float d = TB.dm[1];
                Qmm = d * (s * Qmm);
                cm = c1; smv = s1;
            } else {
                constexpr float d = TB.dm[m];
                Qmm = d * (s * Qmm);
                const float cn = fmaf(cm, c1, -(smv * s1));
                const float sn = fmaf(smv, c1,  (cm * s1));
                cm = cn; smv = sn;
            }

            if constexpr (m == 0) {
                y[0] = Qmm;
            } else {
                y[m * m + 2 * m] = Qmm * cm;
                y[m * m]         = Qmm * smv;
            }

            if constexpr (m + 1 < L) {
                constexpr float e = TB.em[m];
                float Q1 = e * (x * Qmm);
                constexpr int l1 = m + 1;
                if constexpr (m == 0) {
                    y[l1 * l1 + l1] = Q1;
                } else {
                    y[l1 * l1 + l1 + m] = Q1 * cm;
                    y[l1 * l1 + l1 - m] = Q1 * smv;
                }
                float Q2 = Qmm;
                unrolled<m + 2, L>([&](auto lI) {
                    constexpr int l = decltype(lI)::v;
                    constexpr float a = TB.A[l][m];
                    constexpr float b = TB.B[l][m];
                    const float Qn = fmaf(x * Q1, a, b * Q2);
                    if constexpr (m == 0) {
                        y[l * l + l] = Qn;
                    } else {
                        y[l * l + l + m] = Qn * cm;
                        y[l * l + l - m] = Qn * smv;
                    }
                    Q2 = Q1; Q1 = Qn;
                });
            }
        });
    }

    // 25 x STS.128, chunk-major layout: sm[q*QSTR + lane*4 .. +3]
    unrolled<0, CHK>([&](auto qI) {
        constexpr int q = decltype(qI)::v;
        *reinterpret_cast<float4*>(sw + q * QSTR + lane * 4) =
            make_float4(y[4 * q], y[4 * q + 1], y[4 * q + 2], y[4 * q + 3]);
    });

    __syncwarp();

    // ---------------- copy phase: 25 x (LDS.128 + STG.128), fully coalesced ----------------
    float* og = out + (size_t)p0 * NH;

    if (p0 + 32 <= N) {
        #pragma unroll 5
        for (int i = 0; i < CHK; ++i) {
            const int k  = i * 32 + lane;     // flat float4 index within tile (0..799)
            const int pf = k / 25;
            const int q  = k - pf * 25;
            const float4 v = *reinterpret_cast<const float4*>(sw + q * QSTR + pf * 4);
            __stcs(reinterpret_cast<float4*>(og + 4 * k), v);
        }
    } else {
        #pragma unroll 5
        for (int i = 0; i < CHK; ++i) {
            const int k  = i * 32 + lane;
            const int pf = k / 25;
            const int q  = k - pf * 25;
            if (p0 + pf < N) {
                const float4 v = *reinterpret_cast<const float4*>(sw + q * QSTR + pf * 4);
                __stcs(reinterpret_cast<float4*>(og + 4 * k), v);
            }
        }
    }
}

extern "C" void kernel_launch(void* const* d_in, const int* in_sizes, int n_in,
                              void* d_out, int out_size) {
    const float2* ll = (const float2*)d_in[0];
    float* out = (float*)d_out;
    const int N = in_sizes[0] / 2;
    const int grid = (N + NPB - 1) / NPB;
    sh_kernel<<<grid, NPB>>>(ll, out, N);
}